// round 1
// baseline (speedup 1.0000x reference)
#include <cuda_runtime.h>
#include <cuda_bf16.h>

// ============================================================================
// AdaBoost fused classifier:
//   out[n] = sign( sum_e trunc(alpha_e) * (x[n]·W[e] + b[e] > 0) )
// Only estimators with trunc(alpha_e) != 0 matter -> compact them first.
// ============================================================================

#define E_MAX 256
#define F_DIM 512
#define BM 128
#define BN 128
#define BK 16
#define LDS_PAD 132   // BK-row stride (128 + 4 floats pad)

__device__ float g_Wc[E_MAX * F_DIM];   // compacted weight rows
__device__ float g_t[E_MAX];            // trunc(alpha) per compacted slot (0 for pads)
__device__ float g_bc[E_MAX];           // bias per compacted slot
__device__ int   g_idx[E_MAX];          // source estimator index per slot
__device__ int   g_nct;                 // number of 128-col tiles actually needed

// ---------------------------------------------------------------------------
// Kernel 1: deterministic compaction of estimators with trunc(alpha) != 0
// ---------------------------------------------------------------------------
__global__ void compact_kernel(const float* __restrict__ alphas,
                               const float* __restrict__ b) {
    int e = threadIdx.x;            // 256 threads, one per estimator
    float t = truncf(alphas[e]);
    bool p = (t != 0.0f);

    unsigned mask = __ballot_sync(0xffffffffu, p);
    int warp = e >> 5, lane = e & 31;
    __shared__ int wcnt[8];
    if (lane == 0) wcnt[warp] = __popc(mask);
    __syncthreads();

    int off = 0;
    #pragma unroll
    for (int w = 0; w < 8; w++) if (w < warp) off += wcnt[w];
    int pos = off + __popc(mask & ((1u << lane) - 1u));
    if (p) {
        g_idx[pos] = e;
        g_t[pos]   = t;
        g_bc[pos]  = b[e];
    }
    __syncthreads();

    int total = 0;
    #pragma unroll
    for (int w = 0; w < 8; w++) total += wcnt[w];

    // Pad ALL remaining slots (t=0 -> contributes nothing; idx=0 -> safe copy)
    for (int j = total + e; j < E_MAX; j += 256) {
        g_t[j]   = 0.0f;
        g_bc[j]  = 0.0f;
        g_idx[j] = 0;
    }
    if (e == 0) {
        int nct = (total + BN - 1) / BN;
        g_nct = (nct < 1) ? 1 : nct;
    }
}

// ---------------------------------------------------------------------------
// Kernel 2: gather compacted W rows into contiguous scratch
// ---------------------------------------------------------------------------
__global__ void gather_kernel(const float* __restrict__ W) {
    int j   = blockIdx.x;           // 256 blocks, one per slot
    int src = g_idx[j];
    const float4* s = (const float4*)(W + (size_t)src * F_DIM);
    float4*       d = (float4*)(g_Wc + (size_t)j * F_DIM);
    for (int i = threadIdx.x; i < F_DIM / 4; i += blockDim.x) d[i] = s[i];
}

// ---------------------------------------------------------------------------
// Packed-f32x2 helpers (FFMA2 is only reachable via PTX on sm_103a)
// ---------------------------------------------------------------------------
__device__ __forceinline__ unsigned long long pack_dup(float a) {
    unsigned long long d;
    asm("mov.b64 %0, {%1, %1};" : "=l"(d) : "f"(a));
    return d;
}
__device__ __forceinline__ void fma2(unsigned long long& acc,
                                     unsigned long long a,
                                     unsigned long long bb) {
    asm("fma.rn.f32x2 %0, %1, %2, %0;" : "+l"(acc) : "l"(a), "l"(bb));
}
__device__ __forceinline__ void unpack2(unsigned long long v, float& lo, float& hi) {
    asm("mov.b64 {%0, %1}, %2;" : "=f"(lo), "=f"(hi) : "l"(v));
}

// ---------------------------------------------------------------------------
// Kernel 3: main fused GEMM + predicate + weighted sum + sign
//   grid = N/BM blocks, 256 threads (16x16), each thread 8x8 logits
// ---------------------------------------------------------------------------
__global__ __launch_bounds__(256, 2)
void adaboost_main_kernel(const float* __restrict__ x, float* __restrict__ out) {
    __shared__ float As[BK * LDS_PAD];   // [k][row] transposed x tile
    __shared__ float Bs[BK * LDS_PAD];   // [k][col] transposed W tile
    __shared__ float ts[BN];
    __shared__ float bs[BN];
    __shared__ float accRow[BM];

    const int tid = threadIdx.x;
    const int tx  = tid & 15;            // col group
    const int ty  = tid >> 4;            // row group
    const int row0 = blockIdx.x * BM;
    const int nct  = g_nct;

    for (int i = tid; i < BM; i += 256) accRow[i] = 0.0f;
    __syncthreads();

    for (int ct = 0; ct < nct; ct++) {
        if (tid < BN) {
            ts[tid] = g_t[ct * BN + tid];
            bs[tid] = g_bc[ct * BN + tid];
        }

        unsigned long long acc2[8][4];
        #pragma unroll
        for (int i = 0; i < 8; i++)
            #pragma unroll
            for (int j = 0; j < 4; j++) acc2[i][j] = 0ull;

        for (int kt = 0; kt < F_DIM; kt += BK) {
            // --- load A tile (128 rows x 16 k) and B tile, transposed ---
            #pragma unroll
            for (int v = 0; v < 2; v++) {
                int a  = tid + v * 256;          // 0..511 float4 slots
                int r  = a >> 2;                 // row/col 0..127
                int kq = a & 3;                  // k quad 0..3
                float4 fx = *(const float4*)(x + (size_t)(row0 + r) * F_DIM + kt + kq * 4);
                float4 fw = *(const float4*)(g_Wc + (size_t)(ct * BN + r) * F_DIM + kt + kq * 4);
                int kb = kq * 4;
                As[(kb + 0) * LDS_PAD + r] = fx.x;
                As[(kb + 1) * LDS_PAD + r] = fx.y;
                As[(kb + 2) * LDS_PAD + r] = fx.z;
                As[(kb + 3) * LDS_PAD + r] = fx.w;
                Bs[(kb + 0) * LDS_PAD + r] = fw.x;
                Bs[(kb + 1) * LDS_PAD + r] = fw.y;
                Bs[(kb + 2) * LDS_PAD + r] = fw.z;
                Bs[(kb + 3) * LDS_PAD + r] = fw.w;
            }
            __syncthreads();

            // --- 8x8 rank-BK update with packed f32x2 FMAs ---
            #pragma unroll
            for (int kk = 0; kk < BK; kk++) {
                unsigned long long a2[8];
                #pragma unroll
                for (int i = 0; i < 8; i++)
                    a2[i] = pack_dup(As[kk * LDS_PAD + ty * 8 + i]);
                unsigned long long bp[4];
                #pragma unroll
                for (int j = 0; j < 4; j++)
                    bp[j] = *(const unsigned long long*)&Bs[kk * LDS_PAD + tx * 8 + j * 2];
                #pragma unroll
                for (int i = 0; i < 8; i++)
                    #pragma unroll
                    for (int j = 0; j < 4; j++)
                        fma2(acc2[i][j], a2[i], bp[j]);
            }
            __syncthreads();
        }

        // --- epilogue: pred = logit > 0; weighted sum of trunc(alpha) ---
        #pragma unroll
        for (int i = 0; i < 8; i++) {
            float s = 0.0f;
            #pragma unroll
            for (int j = 0; j < 4; j++) {
                float lo, hi;
                unpack2(acc2[i][j], lo, hi);
                int c = tx * 8 + j * 2;
                float l0 = lo + bs[c];
                float l1 = hi + bs[c + 1];
                if (l0 > 0.0f) s += ts[c];
                if (l1 > 0.0f) s += ts[c + 1];
            }
            atomicAdd(&accRow[ty * 8 + i], s);
        }
        __syncthreads();   // accRow & ts stable before next tile / writeout
    }

    if (tid < BM) {
        float a = accRow[tid];
        out[row0 + tid] = (a > 0.0f) ? 1.0f : ((a < 0.0f) ? -1.0f : 0.0f);
    }
}

// ---------------------------------------------------------------------------
extern "C" void kernel_launch(void* const* d_in, const int* in_sizes, int n_in,
                              void* d_out, int out_size) {
    const float* x      = (const float*)d_in[0];   // [131072, 512]
    const float* W      = (const float*)d_in[1];   // [256, 512]
    const float* b      = (const float*)d_in[2];   // [256]
    const float* alphas = (const float*)d_in[3];   // [256]
    float* out = (float*)d_out;                    // [131072]

    int N = in_sizes[0] / F_DIM;                   // 131072

    compact_kernel<<<1, 256>>>(alphas, b);
    gather_kernel<<<E_MAX, 128>>>(W);
    adaboost_main_kernel<<<N / BM, 256>>>(x, out);
}